// round 15
// baseline (speedup 1.0000x reference)
#include <cuda_runtime.h>
#include <cstdint>

// SpectralConv2D, R15: flat two-kernel, K2 reshaped for MLP=9.
//  K1: per input pixel scatter pre-duplicated y{v,v} into tap-major planes
//      g_y[tap][b*900+l]; build g_base[tap][f].
//  K2: thread = (pos-pair, filter-octet): 9 front-batched y LDG.128 (MLP=9),
//      w via LDS, 72 FFMA2, 4 STG.128. No serial chain, one barrier.
//   out[b,l,f] = relu( sum_tap base[f,tap] * y[tap][b,l] )

#define B_    64
#define W_    32
#define C_    8
#define F_    64
#define O2_   30
#define L_    900
#define N_    1024
#define BL_   (B_ * L_)     // 57600

__device__ float2 g_y[9][BL_];        // pre-duplicated y, tap-major (4.15 MB)
__device__ float  g_base[9 * F_];     // [tap][f]

__constant__ int c_sel[9] = {0,1,1,2,0,1,2,2,0};
__constant__ int c_t  [9] = {0,0,1,0,1,2,1,2,2};
__constant__ int c_i  [9] = {0,0,0,1,1,1,2,2,2};
__constant__ int c_j  [9] = {0,1,2,0,1,2,0,1,2};

__device__ __forceinline__ uint64_t ffma2(uint64_t a, uint64_t b, uint64_t c) {
    uint64_t d;
    asm("fma.rn.f32x2 %0, %1, %2, %3;" : "=l"(d) : "l"(a), "l"(b), "l"(c));
    return d;
}
__device__ __forceinline__ uint64_t fmul2(uint64_t a, uint64_t b) {
    uint64_t d;
    asm("mul.rn.f32x2 %0, %1, %2;" : "=l"(d) : "l"(a), "l"(b));
    return d;
}
__device__ __forceinline__ float2 u64_as_f2(uint64_t v) {
    union { uint64_t u; float2 f; } cv; cv.u = v; return cv.f;
}

// ---------------- K1: pixel scatter + base assembly (proven) ----------------
__global__ __launch_bounds__(256)
void prep_kernel(const float* __restrict__ inputs,
                 const float* __restrict__ omega_diag,
                 const float* __restrict__ omega_triu,
                 const float* __restrict__ omega_tril,
                 const float* __restrict__ lambda_in,
                 const float* __restrict__ lambda_out,
                 const float* __restrict__ use_encode,
                 const float* __restrict__ use_decode)
{
    int pid = blockIdx.x * 256 + threadIdx.x;  // 0..65535
    int b = pid >> 10;
    int n = pid & 1023;
    int r = n >> 5;
    int c = n & 31;

    const float4* p = (const float4*)(inputs + (size_t)pid * C_);
    float4 v0 = p[0];
    float4 v1 = p[1];
    float m  = (v0.x + v0.y + v0.z + v0.w + v1.x + v1.y + v1.z + v1.w) * 0.125f;
    float eu = m * __ldg(&use_encode[n]);

    int blb = b * L_;
    #pragma unroll
    for (int tap = 0; tap < 9; tap++) {
        int rr = r - tap / 3;
        int cc = c - tap % 3;
        if (rr >= 0 && rr < O2_ && cc >= 0 && cc < O2_) {
            int l = rr * O2_ + cc;
            float v = eu - __ldg(&use_decode[l]) * m;
            g_y[tap][blb + l] = make_float2(v, v);
        }
    }

    if (blockIdx.x == 0) {
        const float* srcs[3] = { omega_diag, omega_triu, omega_tril };
        for (int idx = threadIdx.x; idx < 9 * F_; idx += 256) {
            int pp = idx >> 6;
            int f  = idx & 63;
            float w   = __ldg(&srcs[c_sel[pp]][f * 3 + c_t[pp]]);
            float lam = __ldg(&lambda_in[c_i[pp]]) - __ldg(&lambda_out[c_j[pp]]);
            g_base[idx] = w * lam;
        }
    }
}

// ---------------- K2: streaming compute, MLP=9 ----------------
// block = 64 consecutive bl; thread = (pp = pos-pair 0..31, f8 = filter-octet 0..7)
__global__ __launch_bounds__(256)
void conv_kernel(float* __restrict__ out)   // (B*L, F)
{
    __shared__ __align__(16) float base_s[9 * F_];

    const int tid = threadIdx.x;
    const int f8  = tid & 7;                // filter octet
    const int pp  = tid >> 3;               // 0..31 -> positions bl0+pp*2, +1
    const int bl0 = blockIdx.x * 64;        // 900 blocks * 64 = 57600 exact
    const int blp = bl0 + pp * 2;

    // ---- front-batched y loads: 9 independent LDG.128 (MLP=9) ----
    ulonglong2 y[9];
    #pragma unroll
    for (int tap = 0; tap < 9; tap++)
        y[tap] = __ldg((const ulonglong2*)&g_y[tap][blp]);  // {v0,v0,v1,v1}

    // coalesced base load while y is in flight
    if (tid < 144)
        ((float4*)base_s)[tid] = __ldg(&((const float4*)g_base)[tid]);
    __syncthreads();

    // ---- 9 taps x (2 pos x 8 filt) FFMA2 ----
    uint64_t acc[2][4];
    #pragma unroll
    for (int tap = 0; tap < 9; tap++) {
        const ulonglong2* wp = (const ulonglong2*)(base_s + tap * F_ + f8 * 8);
        ulonglong2 w0 = wp[0];              // filters f8*8 .. +3
        ulonglong2 w1 = wp[1];              // filters f8*8+4 .. +7
        uint64_t y0 = y[tap].x;             // pos0 duplicated
        uint64_t y1 = y[tap].y;             // pos1 duplicated
        if (tap == 0) {
            acc[0][0] = fmul2(y0, w0.x); acc[0][1] = fmul2(y0, w0.y);
            acc[0][2] = fmul2(y0, w1.x); acc[0][3] = fmul2(y0, w1.y);
            acc[1][0] = fmul2(y1, w0.x); acc[1][1] = fmul2(y1, w0.y);
            acc[1][2] = fmul2(y1, w1.x); acc[1][3] = fmul2(y1, w1.y);
        } else {
            acc[0][0] = ffma2(y0, w0.x, acc[0][0]); acc[0][1] = ffma2(y0, w0.y, acc[0][1]);
            acc[0][2] = ffma2(y0, w1.x, acc[0][2]); acc[0][3] = ffma2(y0, w1.y, acc[0][3]);
            acc[1][0] = ffma2(y1, w0.x, acc[1][0]); acc[1][1] = ffma2(y1, w0.y, acc[1][1]);
            acc[1][2] = ffma2(y1, w1.x, acc[1][2]); acc[1][3] = ffma2(y1, w1.y, acc[1][3]);
        }
    }

    // ---- relu + store: 2 positions x 32B, coalesced across f8 ----
    float* obase = out + (size_t)blp * F_ + f8 * 8;
    #pragma unroll
    for (int k = 0; k < 2; k++) {
        float2 a0 = u64_as_f2(acc[k][0]);
        float2 a1 = u64_as_f2(acc[k][1]);
        float2 a2 = u64_as_f2(acc[k][2]);
        float2 a3 = u64_as_f2(acc[k][3]);
        float4 o0, o1;
        o0.x = fmaxf(a0.x, 0.f); o0.y = fmaxf(a0.y, 0.f);
        o0.z = fmaxf(a1.x, 0.f); o0.w = fmaxf(a1.y, 0.f);
        o1.x = fmaxf(a2.x, 0.f); o1.y = fmaxf(a2.y, 0.f);
        o1.z = fmaxf(a3.x, 0.f); o1.w = fmaxf(a3.y, 0.f);
        float4* op = (float4*)(obase + k * F_);
        op[0] = o0;
        op[1] = o1;
    }
}

extern "C" void kernel_launch(void* const* d_in, const int* in_sizes, int n_in,
                              void* d_out, int out_size) {
    (void)in_sizes; (void)n_in; (void)out_size;
    const float* inputs      = (const float*)d_in[0];
    const float* omega_diag  = (const float*)d_in[1];
    const float* omega_triu  = (const float*)d_in[2];
    const float* omega_tril  = (const float*)d_in[3];
    const float* lambda_in   = (const float*)d_in[4];
    const float* lambda_out  = (const float*)d_in[5];
    const float* use_encode  = (const float*)d_in[6];
    const float* use_decode  = (const float*)d_in[7];
    float* out = (float*)d_out;

    prep_kernel<<<256, 256>>>(inputs, omega_diag, omega_triu, omega_tril,
                              lambda_in, lambda_out, use_encode, use_decode);
    conv_kernel<<<900, 256>>>(out);
}

// round 16
// speedup vs baseline: 1.3988x; 1.3988x over previous
#include <cuda_runtime.h>
#include <cstdint>

// SpectralConv2D fused kernel, R16 = R11 + front-batched y LDS in Phase C.
// All 18 y LDS.128 issued as one independent batch into registers (single
// latency exposure) before the FFMA2 chain; w streamed 1 LDS.128 per tap.
//   out[b,l,f] = relu( sum_tap base[f,tap] * (enc[n]-dec[l]) * up[b,n] )
// Block = (batch b, 2 output rows = 60 positions, 4 input rows = 128 px).

#define B_    64
#define W_    32
#define C_    8
#define F_    64
#define O2_   30
#define L_    900
#define N_    1024
#define TILE  60

__constant__ int c_sel[9] = {0,1,1,2,0,1,2,2,0};
__constant__ int c_t  [9] = {0,0,1,0,1,2,1,2,2};
__constant__ int c_i  [9] = {0,0,0,1,1,1,2,2,2};
__constant__ int c_j  [9] = {0,1,2,0,1,2,0,1,2};

__device__ __forceinline__ uint64_t ffma2(uint64_t a, uint64_t b, uint64_t c) {
    uint64_t d;
    asm("fma.rn.f32x2 %0, %1, %2, %3;" : "=l"(d) : "l"(a), "l"(b), "l"(c));
    return d;
}
__device__ __forceinline__ uint64_t fmul2(uint64_t a, uint64_t b) {
    uint64_t d;
    asm("mul.rn.f32x2 %0, %1, %2;" : "=l"(d) : "l"(a), "l"(b));
    return d;
}
__device__ __forceinline__ float2 u64_as_f2(uint64_t v) {
    union { uint64_t u; float2 f; } cv; cv.u = v; return cv.f;
}

__global__ __launch_bounds__(256)
void spectral_fused_kernel(
    const float* __restrict__ inputs,      // (B, 32, 32, 8)
    const float* __restrict__ omega_diag,  // (F, 3)
    const float* __restrict__ omega_triu,  // (F*3)
    const float* __restrict__ omega_tril,  // (F*3)
    const float* __restrict__ lambda_in,   // (3)
    const float* __restrict__ lambda_out,  // (3)
    const float* __restrict__ use_encode,  // (N)
    const float* __restrict__ use_decode,  // (L)
    float* __restrict__ out)               // (B, L, F)
{
    __shared__ __align__(16) float up_s[128];       // 4 input rows x 32
    __shared__ __align__(16) float eu_s[128];       // enc*up
    __shared__ __align__(16) float dec_s[64];
    __shared__ __align__(16) float base_s[9 * F_];  // [tap][f]
    __shared__ __align__(16) float y_d[9 * 128];    // [tap][pos dup x2], pos 0..63

    const int tid = threadIdx.x;
    const int kt  = blockIdx.x;            // 0..14
    const int b   = blockIdx.y;
    const int r0  = kt * 2;
    const int l0  = kt * TILE;

    // ---------------- Phase A ----------------
    if (tid < 128) {
        int n = r0 * W_ + tid;             // rows r0..r0+3
        const float4* p = (const float4*)(inputs + ((size_t)b * N_ + n) * C_);
        float4 v0 = p[0];
        float4 v1 = p[1];
        float m = (v0.x + v0.y + v0.z + v0.w + v1.x + v1.y + v1.z + v1.w) * 0.125f;
        up_s[tid] = m;
        eu_s[tid] = m * __ldg(&use_encode[n]);
    } else if (tid < 128 + TILE) {
        dec_s[tid - 128] = __ldg(&use_decode[l0 + tid - 128]);
    } else if (tid >= 184) {
        int k = tid - 184;                 // 0..71: zero-pad y positions 60..63
        y_d[(k >> 3) * 128 + 120 + (k & 7)] = 0.f;
    }

    // branchless base assembly: 576 entries over 256 threads, layout [tap][f]
    {
        const float* srcs[3] = { omega_diag, omega_triu, omega_tril };
        #pragma unroll
        for (int k = 0; k < 3; k++) {
            int idx = tid + k * 256;
            if (k < 2 || tid < 64) {
                int pp = idx >> 6;
                int f  = idx & 63;
                float w = __ldg(&srcs[c_sel[pp]][f * 3 + c_t[pp]]);
                float lam = __ldg(&lambda_in[c_i[pp]]) - __ldg(&lambda_out[c_j[pp]]);
                base_s[idx] = w * lam;
            }
        }
    }
    __syncthreads();

    // ---------------- Phase B: duplicated y, one thread per position ----------------
    if (tid < TILE) {
        float dec = dec_s[tid];
        int i0 = (tid >= 30) ? (tid + 2) : tid;    // orow*32 + ocol
        float2* yd = (float2*)y_d;                  // [tap*64 + pos]
        #pragma unroll
        for (int tap = 0; tap < 9; tap++) {
            const int off = (tap / 3) * 32 + (tap % 3);
            float v = eu_s[i0 + off] - dec * up_s[i0 + off];
            yd[tap * 64 + tid] = make_float2(v, v);
        }
    }
    __syncthreads();

    // ---------------- Phase C: front-batched y, streamed w ----------------
    const int f4 = tid & 15;               // filter quad
    const int g  = tid >> 4;               // 0..15 -> positions g*4..g*4+3

    // batch ALL y loads: 18 independent LDS.128 -> one latency exposure
    ulonglong2 yv[9][2];
    #pragma unroll
    for (int tap = 0; tap < 9; tap++) {
        const ulonglong2* yrow = (const ulonglong2*)(y_d + tap * 128 + g * 8);
        yv[tap][0] = yrow[0];              // dup pairs for pos g*4, g*4+1
        yv[tap][1] = yrow[1];              // pos g*4+2, g*4+3
    }

    uint64_t acc[4][2];
    #pragma unroll
    for (int tap = 0; tap < 9; tap++) {
        ulonglong2 wv = *(const ulonglong2*)(base_s + tap * F_ + f4 * 4);
        uint64_t ya = yv[tap][0].x, yb = yv[tap][0].y;
        uint64_t yc = yv[tap][1].x, yd2 = yv[tap][1].y;
        if (tap == 0) {
            acc[0][0] = fmul2(ya,  wv.x); acc[0][1] = fmul2(ya,  wv.y);
            acc[1][0] = fmul2(yb,  wv.x); acc[1][1] = fmul2(yb,  wv.y);
            acc[2][0] = fmul2(yc,  wv.x); acc[2][1] = fmul2(yc,  wv.y);
            acc[3][0] = fmul2(yd2, wv.x); acc[3][1] = fmul2(yd2, wv.y);
        } else {
            acc[0][0] = ffma2(ya,  wv.x, acc[0][0]); acc[0][1] = ffma2(ya,  wv.y, acc[0][1]);
            acc[1][0] = ffma2(yb,  wv.x, acc[1][0]); acc[1][1] = ffma2(yb,  wv.y, acc[1][1]);
            acc[2][0] = ffma2(yc,  wv.x, acc[2][0]); acc[2][1] = ffma2(yc,  wv.y, acc[2][1]);
            acc[3][0] = ffma2(yd2, wv.x, acc[3][0]); acc[3][1] = ffma2(yd2, wv.y, acc[3][1]);
        }
    }

    float* obase = out + ((size_t)b * L_ + l0 + g * 4) * F_ + f4 * 4;
    #pragma unroll
    for (int k = 0; k < 4; k++) {
        int pos = g * 4 + k;
        if (pos < TILE) {
            float2 a0 = u64_as_f2(acc[k][0]);
            float2 a1 = u64_as_f2(acc[k][1]);
            float4 o;
            o.x = fmaxf(a0.x, 0.f);
            o.y = fmaxf(a0.y, 0.f);
            o.z = fmaxf(a1.x, 0.f);
            o.w = fmaxf(a1.y, 0.f);
            *(float4*)(obase + k * F_) = o;
        }
    }
}

extern "C" void kernel_launch(void* const* d_in, const int* in_sizes, int n_in,
                              void* d_out, int out_size) {
    (void)in_sizes; (void)n_in; (void)out_size;
    const float* inputs      = (const float*)d_in[0];
    const float* omega_diag  = (const float*)d_in[1];
    const float* omega_triu  = (const float*)d_in[2];
    const float* omega_tril  = (const float*)d_in[3];
    const float* lambda_in   = (const float*)d_in[4];
    const float* lambda_out  = (const float*)d_in[5];
    const float* use_encode  = (const float*)d_in[6];
    const float* use_decode  = (const float*)d_in[7];
    float* out = (float*)d_out;

    dim3 grid(L_ / TILE, B_);   // (15, 64) = 960 blocks
    spectral_fused_kernel<<<grid, 256>>>(
        inputs, omega_diag, omega_triu, omega_tril,
        lambda_in, lambda_out, use_encode, use_decode, out);
}